// round 2
// baseline (speedup 1.0000x reference)
#include <cuda_runtime.h>
#include <cuda_bf16.h>

#define N_NODES 50000
#define N_EDGES 400000
#define CC 64            // combined output cols: [0,32)=src-proj, [32,64)=dst-proj
#define BLKN 128         // nodes per block
#define KT 32            // k-tile

// 12.8 MB scratch for per-node projections P[n][0..63]
__device__ float g_P[N_NODES * CC];

__device__ __forceinline__ unsigned long long fma2(unsigned long long a,
                                                   unsigned long long b,
                                                   unsigned long long c) {
    unsigned long long d;
    asm("fma.rn.f32x2 %0, %1, %2, %3;" : "=l"(d) : "l"(a), "l"(b), "l"(c));
    return d;
}
__device__ __forceinline__ unsigned long long splat2(float x) {
    unsigned long long d;
    asm("mov.b64 %0, {%1, %1};" : "=l"(d) : "f"(x));
    return d;
}

// P[n][cc] = sum_{k<256} X[n][k] * Wcat[cc][k]  (+ b[cc] for cc<32)
//   X[n][k] = s_{k/64}[n][k%64]
//   Wcat[cc][k] = W[cc][k]        (cc < 32)
//               = W[cc-32][256+k] (cc >= 32)
__global__ __launch_bounds__(BLKN, 4) void node_proj_kernel(
    const float* __restrict__ s0, const float* __restrict__ s1,
    const float* __restrict__ s2, const float* __restrict__ s3,
    const float* __restrict__ W, const float* __restrict__ b)
{
    __shared__ __align__(16) float Xs[KT][BLKN + 4];  // k-major (transposed)
    __shared__ __align__(16) float Ws[KT][CC + 4];    // k-major

    const int tx = threadIdx.x & 7;   // output-col group: cc = tx*8 + c
    const int ty = threadIdx.x >> 3;  // node group: local node = ty*8 + i
    const int nodeBase = blockIdx.x * BLKN;

    // 32 packed accumulators: acc[p][c] = (node 2p, node 2p+1) x col (tx*8+c)
    unsigned long long acc[4][8];
#pragma unroll
    for (int p = 0; p < 4; p++)
#pragma unroll
        for (int c = 0; c < 8; c++) acc[p][c] = 0ull;

    for (int kt = 0; kt < 8; kt++) {
        const float* sj = (kt < 2) ? s0 : ((kt < 4) ? s1 : ((kt < 6) ? s2 : s3));
        const int dbase = (kt & 1) * 32;
        const int ktBase = kt * 32;

        // --- load X tile (transposed to k-major) ---
        int g = nodeBase + (int)threadIdx.x;
        if (g > N_NODES - 1) g = N_NODES - 1;
        const float4* xp = (const float4*)(sj + g * 64 + dbase);
#pragma unroll
        for (int v = 0; v < 8; v++) {
            float4 val = __ldg(&xp[v]);
            Xs[v * 4 + 0][threadIdx.x] = val.x;
            Xs[v * 4 + 1][threadIdx.x] = val.y;
            Xs[v * 4 + 2][threadIdx.x] = val.z;
            Xs[v * 4 + 3][threadIdx.x] = val.w;
        }
        // --- load W tile ---
#pragma unroll
        for (int i = threadIdx.x; i < KT * CC; i += BLKN) {
            int kk = i >> 6, cc = i & 63;
            int row = cc & 31;
            int col = ((cc & 32) ? 256 : 0) + ktBase + kk;
            Ws[kk][cc] = __ldg(&W[row * 512 + col]);
        }
        __syncthreads();

#pragma unroll 8
        for (int kk = 0; kk < KT; kk++) {
            const ulonglong2* xr = (const ulonglong2*)(&Xs[kk][ty * 8]);
            ulonglong2 xa = xr[0];
            ulonglong2 xb = xr[1];
            unsigned long long xpair[4] = {xa.x, xa.y, xb.x, xb.y};
            const float4* wr = (const float4*)(&Ws[kk][tx * 8]);
            float4 w0 = wr[0], w1 = wr[1];
            unsigned long long ws[8] = {
                splat2(w0.x), splat2(w0.y), splat2(w0.z), splat2(w0.w),
                splat2(w1.x), splat2(w1.y), splat2(w1.z), splat2(w1.w)};
#pragma unroll
            for (int p = 0; p < 4; p++)
#pragma unroll
                for (int c = 0; c < 8; c++)
                    acc[p][c] = fma2(xpair[p], ws[c], acc[p][c]);
        }
        __syncthreads();
    }

    // bias folded into the src half (cc < 32) so the edge kernel skips it
    float badd[8];
#pragma unroll
    for (int c = 0; c < 8; c++)
        badd[c] = (tx < 4) ? __ldg(&b[tx * 8 + c]) : 0.0f;

#pragma unroll
    for (int i = 0; i < 8; i++) {
        int node = nodeBase + ty * 8 + i;
        if (node < N_NODES) {
            int p = i >> 1;
            float o[8];
#pragma unroll
            for (int c = 0; c < 8; c++) {
                float2 f = *(float2*)&acc[p][c];
                o[c] = ((i & 1) ? f.y : f.x) + badd[c];
            }
            float4* dstp = (float4*)(&g_P[node * 64 + tx * 8]);
            dstp[0] = make_float4(o[0], o[1], o[2], o[3]);
            dstp[1] = make_float4(o[4], o[5], o[6], o[7]);
        }
    }
}

// out[e][c] = P[src[e]][c] + P[dst[e]][32+c],  c in [0,32). 8 threads/edge, float4 each.
__global__ __launch_bounds__(256) void edge_kernel(
    const int* __restrict__ src, const int* __restrict__ dst,
    float* __restrict__ out)
{
    int tid = blockIdx.x * 256 + threadIdx.x;
    int e = tid >> 3;
    if (e >= N_EDGES) return;
    int q = tid & 7;
    int se = __ldg(&src[e]);
    int de = __ldg(&dst[e]);
    float4 ps = *(const float4*)(&g_P[se * 64 + q * 4]);
    float4 pd = *(const float4*)(&g_P[de * 64 + 32 + q * 4]);
    float4 o = make_float4(ps.x + pd.x, ps.y + pd.y, ps.z + pd.z, ps.w + pd.w);
    *(float4*)(&out[e * 32 + q * 4]) = o;
}

extern "C" void kernel_launch(void* const* d_in, const int* in_sizes, int n_in,
                              void* d_out, int out_size) {
    const float* s0 = (const float*)d_in[0];
    const float* s1 = (const float*)d_in[1];
    const float* s2 = (const float*)d_in[2];
    const float* s3 = (const float*)d_in[3];
    const int*   src = (const int*)d_in[4];
    const int*   dst = (const int*)d_in[5];
    const float* W = (const float*)d_in[6];
    const float* b = (const float*)d_in[7];
    float* out = (float*)d_out;

    node_proj_kernel<<<(N_NODES + BLKN - 1) / BLKN, BLKN>>>(s0, s1, s2, s3, W, b);
    edge_kernel<<<(N_EDGES * 8 + 255) / 256, 256>>>(src, dst, out);
}

// round 7
// speedup vs baseline: 1.3102x; 1.3102x over previous
#include <cuda_runtime.h>
#include <cstdint>

#define N_NODES 50000
#define N_EDGES 400000

// Per-node projections P[n][0..63]: [0,32)=src-half proj, [32,64)=dst-half proj (no bias)
__device__ float g_P[N_NODES * 64];

// ---------------- SMEM layout (dynamic), pitch 528B = 256 bf16 + 16B pad per row ----
// pitch/4 = 132 words == 4 banks mod 32 -> fragment loads hit all 32 banks distinct
#define PITCH    528
#define SM_A_HI  0
#define SM_A_LO  67584            // 128*528
#define SM_B_HI  135168           // + 128*528
#define SM_B_LO  168960           // + 64*528
#define SM_TOTAL 202752           // + 64*528

// split a float4 into packed bf16 hi-pair/lo-pair words (truncation split)
__device__ __forceinline__ void split4(float4 v, uint2* hi, uint2* lo) {
    uint32_t x0 = __float_as_uint(v.x), x1 = __float_as_uint(v.y);
    uint32_t x2 = __float_as_uint(v.z), x3 = __float_as_uint(v.w);
    hi->x = __byte_perm(x0, x1, 0x7632);
    hi->y = __byte_perm(x2, x3, 0x7632);
    float l0 = v.x - __uint_as_float(x0 & 0xFFFF0000u);
    float l1 = v.y - __uint_as_float(x1 & 0xFFFF0000u);
    float l2 = v.z - __uint_as_float(x2 & 0xFFFF0000u);
    float l3 = v.w - __uint_as_float(x3 & 0xFFFF0000u);
    lo->x = __byte_perm(__float_as_uint(l0), __float_as_uint(l1), 0x7632);
    lo->y = __byte_perm(__float_as_uint(l2), __float_as_uint(l3), 0x7632);
}

__device__ __forceinline__ void mma_bf16(float* c, const uint32_t* a, const uint32_t* b) {
    asm volatile(
        "mma.sync.aligned.m16n8k16.row.col.f32.bf16.bf16.f32 "
        "{%0,%1,%2,%3}, {%4,%5,%6,%7}, {%8,%9}, {%0,%1,%2,%3};"
        : "+f"(c[0]), "+f"(c[1]), "+f"(c[2]), "+f"(c[3])
        : "r"(a[0]), "r"(a[1]), "r"(a[2]), "r"(a[3]), "r"(b[0]), "r"(b[1]));
}

// P[n][cc] = sum_{k<256} X[n][k] * Wcat[cc][k]
//   X[n][k] = s_{k/64}[n][k%64]
//   Wcat[cc][k] = W[cc&31][ ((cc&32)?256:0) + k ]
__global__ __launch_bounds__(256, 1) void node_proj_mma(
    const float* __restrict__ s0, const float* __restrict__ s1,
    const float* __restrict__ s2, const float* __restrict__ s3,
    const float* __restrict__ W)
{
    extern __shared__ __align__(16) char smem[];
    const int tid = threadIdx.x;
    const int nodeBase = blockIdx.x * 128;

    // ---- stage A: X tile 128 rows x 256 cols -> bf16 hi/lo (8192 float4) ----
    for (int i = tid; i < 8192; i += 256) {
        int row = i >> 6;
        int kq = (i & 63) << 2;          // k quad base: 0..252
        int node = nodeBase + row;
        if (node > N_NODES - 1) node = N_NODES - 1;
        int s = kq >> 6, j = kq & 63;
        const float* sp = (s < 2) ? (s == 0 ? s0 : s1) : (s == 2 ? s2 : s3);
        float4 v = __ldg((const float4*)(sp + (size_t)node * 64 + j));
        uint2 hi, lo;
        split4(v, &hi, &lo);
        int off = row * PITCH + kq * 2;  // max 127*528 + 504 + 8 = 67568 <= 67584 OK
        *(uint2*)(smem + SM_A_HI + off) = hi;
        *(uint2*)(smem + SM_A_LO + off) = lo;
    }
    // ---- stage B: Wcat 64 rows x 256 cols -> bf16 hi/lo (4096 float4) ----
    for (int i = tid; i < 4096; i += 256) {
        int row = i >> 6;                // cc 0..63
        int kq = (i & 63) << 2;
        int wr = row & 31;
        int kbase = (row & 32) ? 256 : 0;
        float4 v = __ldg((const float4*)(W + (size_t)wr * 512 + kbase + kq));
        uint2 hi, lo;
        split4(v, &hi, &lo);
        int off = row * PITCH + kq * 2;  // max 63*528 + 504 + 8 = 33776 <= 33792 OK
        *(uint2*)(smem + SM_B_HI + off) = hi;
        *(uint2*)(smem + SM_B_LO + off) = lo;
    }
    __syncthreads();

    // ---- warp MMA: warp w owns rows [w*16, w*16+16), all 64 cols ----
    const int wid = tid >> 5;
    const int lane = tid & 31;
    const int g = lane >> 2;        // group id 0..7
    const int tp = (lane & 3) * 2;  // thread pair offset in k

    const int r0 = wid * 16 + g;    // fragment rows r0 and r0+8
    const char* aHi0 = smem + SM_A_HI + r0 * PITCH;
    const char* aHi1 = aHi0 + 8 * PITCH;
    const char* aLo0 = smem + SM_A_LO + r0 * PITCH;
    const char* aLo1 = aLo0 + 8 * PITCH;
    const char* bHiG = smem + SM_B_HI + g * PITCH;   // col n = nt*8 + g
    const char* bLoG = smem + SM_B_LO + g * PITCH;

    float acc[8][4];
#pragma unroll
    for (int nt = 0; nt < 8; nt++)
#pragma unroll
        for (int c = 0; c < 4; c++) acc[nt][c] = 0.0f;

#pragma unroll 2
    for (int ks = 0; ks < 16; ks++) {
        int kb = (ks * 16 + tp) * 2;        // byte offset of this thread's k-pair (max 492)
        uint32_t ah[4], al[4];
        ah[0] = *(const uint32_t*)(aHi0 + kb);
        ah[1] = *(const uint32_t*)(aHi1 + kb);
        ah[2] = *(const uint32_t*)(aHi0 + kb + 16);
        ah[3] = *(const uint32_t*)(aHi1 + kb + 16);
        al[0] = *(const uint32_t*)(aLo0 + kb);
        al[1] = *(const uint32_t*)(aLo1 + kb);
        al[2] = *(const uint32_t*)(aLo0 + kb + 16);
        al[3] = *(const uint32_t*)(aLo1 + kb + 16);
#pragma unroll
        for (int nt = 0; nt < 8; nt++) {
            int boff = nt * 8 * PITCH + kb;
            uint32_t bh[2], bl[2];
            bh[0] = *(const uint32_t*)(bHiG + boff);
            bh[1] = *(const uint32_t*)(bHiG + boff + 16);
            bl[0] = *(const uint32_t*)(bLoG + boff);
            bl[1] = *(const uint32_t*)(bLoG + boff + 16);
            mma_bf16(acc[nt], ah, bh);   // hi*hi
            mma_bf16(acc[nt], ah, bl);   // hi*lo
            mma_bf16(acc[nt], al, bh);   // lo*hi
        }
    }

    // ---- epilogue: fragment -> g_P directly.
    // c0,c1 -> (row r0, cols col,col+1); c2,c3 -> (row r0+8, same cols)
    int node0 = nodeBase + r0;
    int node1 = node0 + 8;
#pragma unroll
    for (int nt = 0; nt < 8; nt++) {
        int col = nt * 8 + tp;
        if (node0 < N_NODES)
            *(float2*)(g_P + (size_t)node0 * 64 + col) = make_float2(acc[nt][0], acc[nt][1]);
        if (node1 < N_NODES)
            *(float2*)(g_P + (size_t)node1 * 64 + col) = make_float2(acc[nt][2], acc[nt][3]);
    }
}

// out[e][c] = P[src[e]][c] + P[dst[e]][32+c] + b[c]; 8 threads/edge, 2 edges/thread
__global__ __launch_bounds__(256) void edge_kernel(
    const int* __restrict__ src, const int* __restrict__ dst,
    const float* __restrict__ b, float* __restrict__ out)
{
    int tid = blockIdx.x * 256 + threadIdx.x;
    int q = tid & 7;
    int e0 = tid >> 3;
    if (e0 >= N_EDGES / 2) return;
    int e1 = e0 + (N_EDGES / 2);
    float4 bv = __ldg((const float4*)b + q);
    int s0i = __ldg(src + e0), d0i = __ldg(dst + e0);
    int s1i = __ldg(src + e1), d1i = __ldg(dst + e1);
    float4 a0 = __ldg((const float4*)(g_P + (size_t)s0i * 64 + q * 4));
    float4 c0 = __ldg((const float4*)(g_P + (size_t)d0i * 64 + 32 + q * 4));
    float4 a1 = __ldg((const float4*)(g_P + (size_t)s1i * 64 + q * 4));
    float4 c1 = __ldg((const float4*)(g_P + (size_t)d1i * 64 + 32 + q * 4));
    float4 o0 = make_float4(a0.x + c0.x + bv.x, a0.y + c0.y + bv.y,
                            a0.z + c0.z + bv.z, a0.w + c0.w + bv.w);
    float4 o1 = make_float4(a1.x + c1.x + bv.x, a1.y + c1.y + bv.y,
                            a1.z + c1.z + bv.z, a1.w + c1.w + bv.w);
    *(float4*)(out + (size_t)e0 * 32 + q * 4) = o0;
    *(float4*)(out + (size_t)e1 * 32 + q * 4) = o1;
}

extern "C" void kernel_launch(void* const* d_in, const int* in_sizes, int n_in,
                              void* d_out, int out_size) {
    const float* s0 = (const float*)d_in[0];
    const float* s1 = (const float*)d_in[1];
    const float* s2 = (const float*)d_in[2];
    const float* s3 = (const float*)d_in[3];
    const int*   src = (const int*)d_in[4];
    const int*   dst = (const int*)d_in[5];
    const float* W = (const float*)d_in[6];
    const float* b = (const float*)d_in[7];
    float* out = (float*)d_out;

    // unconditional (no static guards); non-stream API, capture-safe, idempotent
    cudaFuncSetAttribute(node_proj_mma, cudaFuncAttributeMaxDynamicSharedMemorySize,
                         SM_TOTAL);

    node_proj_mma<<<(N_NODES + 127) / 128, 256, SM_TOTAL>>>(s0, s1, s2, s3, W);
    edge_kernel<<<(N_EDGES / 2 * 8 + 255) / 256, 256>>>(src, dst, b, out);
}